// round 10
// baseline (speedup 1.0000x reference)
#include <cuda_runtime.h>
#include <cstdint>

// Problem constants (fixed-shape problem: H=8, MH=8, N_NODES=500000)
#define H_DIM 8
#define MH_DIM 8
#define FEAT 64              // H*MH per sign
#define MAX_NODES 500000
#define MAX_NQ 500000
#define BKT 64               // nodes per bucket
#define MAX_NB ((MAX_NODES + BKT - 1) / BKT)   // 7813

// Sorting scratch (static, reused deterministically each replay)
__device__ int  g_hist[MAX_NB];
__device__ int  g_off[MAX_NB + 1];
__device__ int  g_cursor[MAX_NB];
__device__ int2 g_sorted[MAX_NQ];    // (query id, node id)

// Swizzled byte offset of (feat f, node n) in the 128x64 float tile
// (row = 256B). Conflict-free strided stores; bounded conflicts on
// transpose-reads (bits[6:4] ^= bits[9:7]^bits[13:11]).
__device__ __forceinline__ int sw_byte(int f, int n) {
    int off = f * 256 + n * 4;
    int x = ((off >> 7) ^ (off >> 11)) & 7;
    return off ^ (x << 4);
}

// ---------------- sort pipeline ----------------
__global__ void zero_hist_kernel(int nb) {
    int i = blockIdx.x * blockDim.x + threadIdx.x;
    if (i < nb) g_hist[i] = 0;
}

__global__ void hist_kernel(const int* __restrict__ k_indices, int nq) {
    int i = blockIdx.x * blockDim.x + threadIdx.x;
    if (i < nq) atomicAdd(&g_hist[__ldcs(k_indices + i) / BKT], 1);
}

__global__ __launch_bounds__(1024) void scan_kernel(int nb) {
    __shared__ int part[1024];
    int t = threadIdx.x;
    int base = t * 8;
    int local[8];
    int s = 0;
    #pragma unroll
    for (int j = 0; j < 8; ++j) {
        local[j] = s;
        int idx = base + j;
        s += (idx < nb) ? g_hist[idx] : 0;
    }
    part[t] = s;
    __syncthreads();
    for (int off = 1; off < 1024; off <<= 1) {
        int v = (t >= off) ? part[t - off] : 0;
        __syncthreads();
        part[t] += v;
        __syncthreads();
    }
    int excl = (t == 0) ? 0 : part[t - 1];
    #pragma unroll
    for (int j = 0; j < 8; ++j) {
        int idx = base + j;
        if (idx < nb) {
            int o = excl + local[j];
            g_off[idx] = o;
            g_cursor[idx] = o;
        }
    }
    if (t == 1023) g_off[nb] = part[1023];
}

__global__ void scatter_kernel(const int* __restrict__ k_indices, int nq) {
    int i = blockIdx.x * blockDim.x + threadIdx.x;
    if (i < nq) {
        int k = __ldcs(k_indices + i);
        int slot = atomicAdd(&g_cursor[k / BKT], 1);
        g_sorted[slot] = make_int2(i, k);
    }
}

// ---------------------------------------------------------------------------
// Fused kernel: block b owns nodes [64b, 64b+64).
// Phase 1: load phi tile (128 feats x 64 nodes) into swizzled smem, folding
//          1/max(deg,1) at load time (all fp32).
// Phase 2: walk this bucket's sorted queries: 8 threads/query (thread = head),
//          gather q (2x float4), dot against smem columns, scatter out.
// out layout: [pos: nq*8][neg: nq*8]
// ---------------------------------------------------------------------------
__global__ __launch_bounds__(256) void fused_kernel(
    const float* __restrict__ q_phi,
    const float* __restrict__ phi_pos,
    const float* __restrict__ phi_neg,
    const float* __restrict__ deg_pos,
    const float* __restrict__ deg_neg,
    float* __restrict__ out,
    int nq, int n_nodes)
{
    __shared__ __align__(16) char tile_raw[128 * 256];   // 32KB fp32, scaled
    __shared__ float inv[2][BKT][H_DIM];                 // 4KB

    const int b  = blockIdx.x;
    const int k0 = b * BKT;
    const int t  = threadIdx.x;

    const int qs = g_off[b];
    const int qe = g_off[b + 1];
    if (qs == qe) return;                 // no queries -> skip tile entirely

    // ---- inv table: 2*64*8 = 1024 values ----
    #pragma unroll
    for (int it = 0; it < 4; ++it) {
        int idx  = t + it * 256;          // s*512 + node*8 + h
        int s    = idx >> 9;
        int node = (idx >> 3) & 63;
        int h    = idx & 7;
        int k    = k0 + node;
        float d  = 1.0f;
        if (k < n_nodes) {
            const float* dp = s ? deg_neg : deg_pos;
            d = __ldcs(dp + (size_t)k * H_DIM + h);
        }
        inv[s][node][h] = 1.0f / fmaxf(d, 1.0f);
    }
    __syncthreads();

    // ---- phase 1: strided phi load, fold inv, swizzled store ----
    const bool full = (k0 + BKT <= n_nodes) && ((n_nodes & 3) == 0);
    if (full) {
        #pragma unroll
        for (int it = 0; it < 8; ++it) {
            int l = t + it * 256;         // 0..2047
            int r = l >> 4;               // feat row 0..127
            int g = l & 15;               // float4 group (4 nodes)
            int s = r >> 6;
            int f = r & 63;
            int h = f >> 3;
            const float* src = s ? phi_neg : phi_pos;
            float4 v = __ldcs(reinterpret_cast<const float4*>(
                src + (size_t)f * n_nodes + k0 + 4 * g));
            int n0 = 4 * g;
            v.x *= inv[s][n0 + 0][h];
            v.y *= inv[s][n0 + 1][h];
            v.z *= inv[s][n0 + 2][h];
            v.w *= inv[s][n0 + 3][h];
            *reinterpret_cast<float4*>(tile_raw + sw_byte(r, n0)) = v;
        }
    } else {
        #pragma unroll 4
        for (int it = 0; it < 32; ++it) {
            int l  = t + it * 256;        // 8192 elements
            int r  = l >> 6;
            int kk = l & 63;
            int k  = k0 + kk;
            int s  = r >> 6;
            int f  = r & 63;
            int h  = f >> 3;
            float v = 0.0f;
            if (k < n_nodes) {
                const float* src = s ? phi_neg : phi_pos;
                v = __ldcs(src + (size_t)f * n_nodes + k) * inv[s][kk][h];
            }
            *reinterpret_cast<float*>(tile_raw + sw_byte(r, kk)) = v;
        }
    }
    __syncthreads();

    // ---- phase 2: query loop, 32 groups of 8 threads ----
    const int group = t >> 3;
    const int h     = t & 7;
    for (int idx = qs + group; idx < qe; idx += 32) {
        int2 ik  = g_sorted[idx];
        int  i   = ik.x;
        int  node = ik.y - k0;

        const float4* qp = reinterpret_cast<const float4*>(
            q_phi + (size_t)i * FEAT + h * MH_DIM);
        float4 q0 = __ldcs(qp);
        float4 q1 = __ldcs(qp + 1);

        float dp = 0.0f, dn = 0.0f;
        #pragma unroll
        for (int j = 0; j < 4; ++j) {
            float qj = (&q0.x)[j];
            dp += qj * *reinterpret_cast<const float*>(
                           tile_raw + sw_byte(8 * h + j, node));
            dn += qj * *reinterpret_cast<const float*>(
                           tile_raw + sw_byte(64 + 8 * h + j, node));
        }
        #pragma unroll
        for (int j = 0; j < 4; ++j) {
            float qj = (&q1.x)[j];
            dp += qj * *reinterpret_cast<const float*>(
                           tile_raw + sw_byte(8 * h + 4 + j, node));
            dn += qj * *reinterpret_cast<const float*>(
                           tile_raw + sw_byte(64 + 8 * h + 4 + j, node));
        }

        __stcs(out + (size_t)i * H_DIM + h, dp);
        __stcs(out + (size_t)nq * H_DIM + (size_t)i * H_DIM + h, dn);
    }
}

extern "C" void kernel_launch(void* const* d_in, const int* in_sizes, int n_in,
                              void* d_out, int out_size)
{
    const float* q_phi   = (const float*)d_in[0];
    const float* phi_pos = (const float*)d_in[1];
    const float* phi_neg = (const float*)d_in[2];
    const float* deg_pos = (const float*)d_in[3];
    const float* deg_neg = (const float*)d_in[4];
    const int*   k_idx   = (const int*)d_in[5];

    int nq      = in_sizes[5];
    int n_nodes = in_sizes[3] / H_DIM;
    if (n_nodes > MAX_NODES) n_nodes = MAX_NODES;
    if (nq > MAX_NQ) nq = MAX_NQ;

    int nb = (n_nodes + BKT - 1) / BKT;

    zero_hist_kernel<<<(nb + 255) / 256, 256>>>(nb);
    hist_kernel<<<(nq + 255) / 256, 256>>>(k_idx, nq);
    scan_kernel<<<1, 1024>>>(nb);
    scatter_kernel<<<(nq + 255) / 256, 256>>>(k_idx, nq);
    fused_kernel<<<nb, 256>>>(q_phi, phi_pos, phi_neg, deg_pos, deg_neg,
                              (float*)d_out, nq, n_nodes);
}